// round 2
// baseline (speedup 1.0000x reference)
#include <cuda_runtime.h>
#include <math.h>

#define BB 2
#define SS 2048
#define EE 768
#define HH 12
#define DD 64
#define MT (BB*SS)

// Scratch (allocation-free rule: __device__ globals)
__device__ float g_q[(size_t)BB*HH*SS*DD];
__device__ float g_k[(size_t)BB*HH*SS*DD];
__device__ float g_v[(size_t)BB*HH*SS*DD];
__device__ float g_attn[(size_t)BB*SS*EE];

// ---------------------------------------------------------------------------
// GEMM: C = A[M,768] @ W[768,768] + bias, 128x128x16 tiles, 8x8 per thread.
// MODE 0: write C[m*EE+n].  MODE 1: write to [B,H,S,D] layout (head transpose).
// blockIdx.z selects (W,b,out) set (used to fuse Q/K/V projections).
// ---------------------------------------------------------------------------
template<int MODE>
__global__ __launch_bounds__(256)
void gemm128(const float* __restrict__ A,
             const float* __restrict__ W0, const float* __restrict__ b0,
             const float* __restrict__ W1, const float* __restrict__ b1,
             const float* __restrict__ W2, const float* __restrict__ b2,
             float* o0, float* o1, float* o2)
{
    const float* W; const float* bias; float* out;
    if (blockIdx.z == 0)      { W = W0; bias = b0; out = o0; }
    else if (blockIdx.z == 1) { W = W1; bias = b1; out = o1; }
    else                      { W = W2; bias = b2; out = o2; }

    __shared__ float As[16][132];   // [k][m], padded (132 % 4 == 0 keeps 16B align)
    __shared__ float Bs[16][128];   // [k][n]

    const int tx = threadIdx.x & 15;
    const int ty = threadIdx.x >> 4;
    const int m0 = blockIdx.y * 128;
    const int n0 = blockIdx.x * 128;

    float acc[8][8];
#pragma unroll
    for (int r = 0; r < 8; r++)
#pragma unroll
        for (int c = 0; c < 8; c++) acc[r][c] = 0.f;

    for (int k0 = 0; k0 < EE; k0 += 16) {
        // Load A tile 128x16, store transposed into As[k][m]
#pragma unroll
        for (int i = 0; i < 2; i++) {
            int idx = threadIdx.x + i * 256;       // 0..511
            int row = idx >> 2;                    // 0..127
            int kk4 = (idx & 3) * 4;               // 0,4,8,12
            float4 a = *(const float4*)&A[(size_t)(m0 + row) * EE + k0 + kk4];
            As[kk4 + 0][row] = a.x;
            As[kk4 + 1][row] = a.y;
            As[kk4 + 2][row] = a.z;
            As[kk4 + 3][row] = a.w;
        }
        // Load B tile 16x128 straight in
#pragma unroll
        for (int i = 0; i < 2; i++) {
            int idx = threadIdx.x + i * 256;
            int row = idx >> 5;                    // 0..15
            int c4  = (idx & 31) * 4;              // 0..124
            *(float4*)&Bs[row][c4] = *(const float4*)&W[(size_t)(k0 + row) * EE + n0 + c4];
        }
        __syncthreads();

#pragma unroll
        for (int kk = 0; kk < 16; kk++) {
            float4 a0 = *(float4*)&As[kk][ty * 8];
            float4 a1 = *(float4*)&As[kk][ty * 8 + 4];
            float4 bb0 = *(float4*)&Bs[kk][tx * 8];
            float4 bb1 = *(float4*)&Bs[kk][tx * 8 + 4];
            float ar[8] = {a0.x, a0.y, a0.z, a0.w, a1.x, a1.y, a1.z, a1.w};
            float br[8] = {bb0.x, bb0.y, bb0.z, bb0.w, bb1.x, bb1.y, bb1.z, bb1.w};
#pragma unroll
            for (int r = 0; r < 8; r++)
#pragma unroll
                for (int c = 0; c < 8; c++)
                    acc[r][c] = fmaf(ar[r], br[c], acc[r][c]);
        }
        __syncthreads();
    }

    // Epilogue: bias + store
#pragma unroll
    for (int r = 0; r < 8; r++) {
        int m = m0 + ty * 8 + r;
#pragma unroll
        for (int c = 0; c < 8; c++) {
            int n = n0 + tx * 8 + c;
            float val = acc[r][c] + bias[n];
            if (MODE == 0) {
                out[(size_t)m * EE + n] = val;
            } else {
                int b_ = m >> 11;          // m / SS
                int s  = m & (SS - 1);
                int h  = n >> 6;           // n / DD
                int d  = n & (DD - 1);
                out[(((size_t)(b_ * HH + h)) * SS + s) * DD + d] = val;
            }
        }
    }
}

// ---------------------------------------------------------------------------
// RoPE in-place on q,k in [B,H,S,D] layout. One thread per (bh, s, pair i).
// pair (i, i+32):  out[i]   = x[i]*cos - x[i+32]*sin
//                  out[i+32]= x[i+32]*cos + x[i]*sin ,  angle = s * 10000^{-i/32}
// ---------------------------------------------------------------------------
__global__ __launch_bounds__(256)
void rope_kernel(float* __restrict__ q, float* __restrict__ k)
{
    int idx = blockIdx.x * blockDim.x + threadIdx.x;   // < BB*HH*SS*32
    int i  = idx & 31;
    int s  = (idx >> 5) & (SS - 1);
    int bh = idx >> 16;                                 // 32*2048 = 2^16

    // ln(10000)/32 = 0.28782313662425572
    float inv = expf(-(float)i * 0.28782313662425572f);
    float ang = (float)s * inv;
    float c, sn;
    sincosf(ang, &sn, &c);

    size_t base = ((size_t)bh * SS + s) * DD;
    float* qr = q + base;
    float* kr = k + base;

    float qa = qr[i], qb = qr[i + 32];
    qr[i]      = qa * c - qb * sn;
    qr[i + 32] = qb * c + qa * sn;

    float ka = kr[i], kb = kr[i + 32];
    kr[i]      = ka * c - kb * sn;
    kr[i + 32] = kb * c + ka * sn;
}

// ---------------------------------------------------------------------------
// Flash attention, causal. One block per (q-tile of 64 rows, b*h).
// 256 threads = 16x16, each thread owns a 4x4 micro-tile.
// Smem layouts chosen so inner-loop LDS are broadcast or 2-way at worst:
//   Qs[d][m], Ks[d][n] (reused as Ps[n][m]), Vs[n][d].
// ---------------------------------------------------------------------------
#define ATTN_SMEM_FLOATS (2*64*65 + 64*64)
#define ATTN_SMEM_BYTES  (ATTN_SMEM_FLOATS * 4)

__global__ __launch_bounds__(256)
void attn_kernel(const float* __restrict__ q, const float* __restrict__ k,
                 const float* __restrict__ v, float* __restrict__ out)
{
    extern __shared__ float sm[];
    float (*Qs)[65] = (float(*)[65])sm;              // [d][m]
    float (*Ks)[65] = (float(*)[65])(sm + 64 * 65);  // [d][n]; reused as Ps[n][m]
    float (*Vs)[64] = (float(*)[64])(sm + 2 * 64 * 65); // [n][d]

    const int mt = blockIdx.x;
    const int bh = blockIdx.y;
    const int m0 = mt * 64;
    const float* qp = q + (size_t)bh * SS * DD;
    const float* kp = k + (size_t)bh * SS * DD;
    const float* vp = v + (size_t)bh * SS * DD;

    const int tid = threadIdx.x;
    const int tx = tid & 15;
    const int ty = tid >> 4;

    // Load Q tile transposed: Qs[d][m]
#pragma unroll
    for (int i = 0; i < 4; i++) {
        int idx = tid + i * 256;           // 0..1023  (64 rows * 16 float4)
        int r  = idx >> 4;
        int d4 = (idx & 15) * 4;
        float4 a = *(const float4*)&qp[(size_t)(m0 + r) * DD + d4];
        Qs[d4 + 0][r] = a.x;
        Qs[d4 + 1][r] = a.y;
        Qs[d4 + 2][r] = a.z;
        Qs[d4 + 3][r] = a.w;
    }

    float mi[4], li[4], acc[4][4];
#pragma unroll
    for (int r = 0; r < 4; r++) {
        mi[r] = -1e30f; li[r] = 0.f;
#pragma unroll
        for (int c = 0; c < 4; c++) acc[r][c] = 0.f;
    }

    for (int nt = 0; nt <= mt; nt++) {
        __syncthreads();   // prior PV done reading Vs/Ps
        int n0 = nt * 64;
        // Load K tile transposed (Ks[d][n]) and V tile straight (Vs[n][d])
#pragma unroll
        for (int i = 0; i < 4; i++) {
            int idx = tid + i * 256;
            int r  = idx >> 4;
            int d4 = (idx & 15) * 4;
            float4 a = *(const float4*)&kp[(size_t)(n0 + r) * DD + d4];
            Ks[d4 + 0][r] = a.x;
            Ks[d4 + 1][r] = a.y;
            Ks[d4 + 2][r] = a.z;
            Ks[d4 + 3][r] = a.w;
            float4 b = *(const float4*)&vp[(size_t)(n0 + r) * DD + d4];
            *(float4*)&Vs[r][d4] = b;
        }
        __syncthreads();

        // S = Q @ K^T  (per-thread 4x4)
        float sc[4][4];
#pragma unroll
        for (int r = 0; r < 4; r++)
#pragma unroll
            for (int c = 0; c < 4; c++) sc[r][c] = 0.f;

#pragma unroll 8
        for (int d = 0; d < 64; d++) {
            float qv[4], kv[4];
#pragma unroll
            for (int r = 0; r < 4; r++) qv[r] = Qs[d][ty * 4 + r];
#pragma unroll
            for (int c = 0; c < 4; c++) kv[c] = Ks[d][tx * 4 + c];
#pragma unroll
            for (int r = 0; r < 4; r++)
#pragma unroll
                for (int c = 0; c < 4; c++)
                    sc[r][c] = fmaf(qv[r], kv[c], sc[r][c]);
        }

        // scale + causal mask (only diagonal tile needs masking)
#pragma unroll
        for (int r = 0; r < 4; r++)
#pragma unroll
            for (int c = 0; c < 4; c++) {
                sc[r][c] *= 0.125f;   // 1/sqrt(64)
                if (nt == mt && (tx * 4 + c) > (ty * 4 + r)) sc[r][c] = -1e30f;
            }

        // online softmax update (row stats replicated across the 16 tx lanes)
#pragma unroll
        for (int r = 0; r < 4; r++) {
            float tm = sc[r][0];
#pragma unroll
            for (int c = 1; c < 4; c++) tm = fmaxf(tm, sc[r][c]);
#pragma unroll
            for (int msk = 8; msk >= 1; msk >>= 1)
                tm = fmaxf(tm, __shfl_xor_sync(0xffffffffu, tm, msk));
            float mn = fmaxf(mi[r], tm);
            float alpha = expf(mi[r] - mn);
            float rs = 0.f;
#pragma unroll
            for (int c = 0; c < 4; c++) {
                float p = expf(sc[r][c] - mn);
                sc[r][c] = p;
                rs += p;
            }
#pragma unroll
            for (int msk = 8; msk >= 1; msk >>= 1)
                rs += __shfl_xor_sync(0xffffffffu, rs, msk);
            li[r] = li[r] * alpha + rs;
            mi[r] = mn;
#pragma unroll
            for (int c = 0; c < 4; c++) acc[r][c] *= alpha;
        }

        __syncthreads();   // all QK reads of Ks finished
        // write P into Ks storage as Ps[n][m]
#pragma unroll
        for (int r = 0; r < 4; r++)
#pragma unroll
            for (int c = 0; c < 4; c++)
                Ks[tx * 4 + c][ty * 4 + r] = sc[r][c];
        __syncthreads();

        // O += P @ V
#pragma unroll 8
        for (int n = 0; n < 64; n++) {
            float pv[4], vv[4];
#pragma unroll
            for (int r = 0; r < 4; r++) pv[r] = Ks[n][ty * 4 + r];
#pragma unroll
            for (int c = 0; c < 4; c++) vv[c] = Vs[n][tx * 4 + c];
#pragma unroll
            for (int r = 0; r < 4; r++)
#pragma unroll
                for (int c = 0; c < 4; c++)
                    acc[r][c] = fmaf(pv[r], vv[c], acc[r][c]);
        }
    }

    // normalize + write to [B,S,E]
    const int b_ = bh / HH;
    const int h  = bh % HH;
#pragma unroll
    for (int r = 0; r < 4; r++) {
        float invl = 1.f / li[r];
        int m = m0 + ty * 4 + r;
#pragma unroll
        for (int c = 0; c < 4; c++)
            out[((size_t)(b_ * SS + m)) * EE + h * DD + tx * 4 + c] = acc[r][c] * invl;
    }
}

// ---------------------------------------------------------------------------
extern "C" void kernel_launch(void* const* d_in, const int* in_sizes, int n_in,
                              void* d_out, int out_size)
{
    (void)in_sizes; (void)n_in; (void)out_size;
    const float* x  = (const float*)d_in[0];
    const float* Wq = (const float*)d_in[1];
    const float* bq = (const float*)d_in[2];
    const float* Wk = (const float*)d_in[3];
    const float* bk = (const float*)d_in[4];
    const float* Wv = (const float*)d_in[5];
    const float* bv = (const float*)d_in[6];
    const float* Wp = (const float*)d_in[7];
    const float* bp = (const float*)d_in[8];

    float *q, *k, *v, *attn;
    cudaGetSymbolAddress((void**)&q,    g_q);
    cudaGetSymbolAddress((void**)&k,    g_k);
    cudaGetSymbolAddress((void**)&v,    g_v);
    cudaGetSymbolAddress((void**)&attn, g_attn);

    cudaFuncSetAttribute(attn_kernel,
                         cudaFuncAttributeMaxDynamicSharedMemorySize,
                         ATTN_SMEM_BYTES);

    // Fused Q/K/V projections (blockIdx.z selects the weight set), writes [B,H,S,D]
    gemm128<1><<<dim3(EE / 128, MT / 128, 3), 256>>>(
        x, Wq, bq, Wk, bk, Wv, bv, q, k, v);

    // RoPE in place on q,k
    rope_kernel<<<(BB * HH * SS * 32) / 256, 256>>>(q, k);

    // Causal flash attention -> g_attn [B,S,E]
    attn_kernel<<<dim3(SS / 64, BB * HH), 256, ATTN_SMEM_BYTES>>>(q, k, v, attn);

    // Output projection -> d_out
    gemm128<0><<<dim3(EE / 128, MT / 128, 1), 256>>>(
        attn, Wp, bp, Wp, bp, Wp, bp, (float*)d_out, (float*)d_out, (float*)d_out);
}

// round 6
// speedup vs baseline: 1.2843x; 1.2843x over previous
#include <cuda_runtime.h>
#include <cuda_bf16.h>
#include <math.h>
#include <stdint.h>

#define BB 2
#define SS 2048
#define EE 768
#define HH 12
#define DD 64
#define MT (BB*SS)

// ---------------------------------------------------------------------------
// Scratch (allocation-free rule: __device__ globals)
// ---------------------------------------------------------------------------
__device__ float g_q[(size_t)BB*HH*SS*DD];
__device__ float g_k[(size_t)BB*HH*SS*DD];
__device__ float g_v[(size_t)BB*HH*SS*DD];
__device__ float g_attn[(size_t)BB*SS*EE];
__device__ __nv_bfloat16 g_ah[(size_t)MT*EE];
__device__ __nv_bfloat16 g_al[(size_t)MT*EE];
__device__ __nv_bfloat16 g_wth[(size_t)4*EE*EE];   // [4][n][k] = W[k][n] hi
__device__ __nv_bfloat16 g_wtl[(size_t)4*EE*EE];   // lo

// ---------------------------------------------------------------------------
// PTX helpers (BASE ISA ONLY — harness ptxas targets sm_103 without 'a',
// so no tcgen05/TMEM. cp.async + ldmatrix + mma.sync are base sm_80+.)
// ---------------------------------------------------------------------------
__device__ __forceinline__ uint32_t smem_u32(const void* p) {
    uint32_t a;
    asm("{ .reg .u64 t; cvta.to.shared.u64 t, %1; cvt.u32.u64 %0, t; }"
        : "=r"(a) : "l"(p));
    return a;
}
__device__ __forceinline__ void cp_async16(uint32_t saddr, const void* gaddr) {
    asm volatile("cp.async.cg.shared.global [%0], [%1], 16;"
                 :: "r"(saddr), "l"(gaddr) : "memory");
}
__device__ __forceinline__ void cp_commit() {
    asm volatile("cp.async.commit_group;" ::: "memory");
}
__device__ __forceinline__ void cp_wait1() {
    asm volatile("cp.async.wait_group 1;" ::: "memory");
}
__device__ __forceinline__ void ldsm_x4(uint32_t* r, uint32_t addr) {
    asm volatile("ldmatrix.sync.aligned.m8n8.x4.shared.b16 {%0,%1,%2,%3}, [%4];"
                 : "=r"(r[0]), "=r"(r[1]), "=r"(r[2]), "=r"(r[3]) : "r"(addr));
}
__device__ __forceinline__ void mma16816(float* c, const uint32_t* a,
                                         uint32_t b0, uint32_t b1) {
    asm volatile(
        "mma.sync.aligned.m16n8k16.row.col.f32.bf16.bf16.f32 "
        "{%0,%1,%2,%3}, {%4,%5,%6,%7}, {%8,%9}, {%0,%1,%2,%3};"
        : "+f"(c[0]), "+f"(c[1]), "+f"(c[2]), "+f"(c[3])
        : "r"(a[0]), "r"(a[1]), "r"(a[2]), "r"(a[3]), "r"(b0), "r"(b1));
}

// ---------------------------------------------------------------------------
// Precision-split conversion: x -> (bf16 hi, bf16 lo)
// ---------------------------------------------------------------------------
__global__ __launch_bounds__(256)
void split_convert(const float* __restrict__ in, __nv_bfloat16* __restrict__ h,
                   __nv_bfloat16* __restrict__ l, int n)
{
    int i = blockIdx.x * blockDim.x + threadIdx.x;
    if (i < n) {
        float x = in[i];
        __nv_bfloat16 hi = __float2bfloat16(x);
        float r = x - __bfloat162float(hi);
        h[i] = hi;
        l[i] = __float2bfloat16(r);
    }
}

// Transpose + split: Wt[z][n][k] = W_z[k][n]  (hi/lo bf16)
__global__ __launch_bounds__(256)
void transpose_split(const float* __restrict__ W0, const float* __restrict__ W1,
                     const float* __restrict__ W2, const float* __restrict__ W3,
                     __nv_bfloat16* __restrict__ th, __nv_bfloat16* __restrict__ tl)
{
    __shared__ float t[32][33];
    const float* W = (blockIdx.z == 0) ? W0 : (blockIdx.z == 1) ? W1
                   : (blockIdx.z == 2) ? W2 : W3;
    int n0 = blockIdx.x * 32, k0 = blockIdx.y * 32;
    int tx = threadIdx.x & 31, ty = threadIdx.x >> 5;
#pragma unroll
    for (int i = 0; i < 4; i++)
        t[ty + 8 * i][tx] = W[(size_t)(k0 + ty + 8 * i) * EE + n0 + tx];
    __syncthreads();
    size_t base = (size_t)blockIdx.z * EE * EE;
#pragma unroll
    for (int i = 0; i < 4; i++) {
        int row = ty + 8 * i;                 // local n
        float x = t[tx][row];                 // = W[k0+tx][n0+row]
        __nv_bfloat16 hi = __float2bfloat16(x);
        float r = x - __bfloat162float(hi);
        size_t o = base + (size_t)(n0 + row) * EE + k0 + tx;
        th[o] = hi;
        tl[o] = __float2bfloat16(r);
    }
}

// ---------------------------------------------------------------------------
// mma.sync GEMM: C[M,768] = A[M,768] @ W[768,768] + bias  (bf16x3 split)
// CTA 128x128, 8 warps of 32x64, K-chunk 32, 3-stage cp.async pipeline.
// Smem row pitch 80B -> ldmatrix row banks r*20%32 all distinct (conflict-free).
// MODE 0: C[m*EE+n].  MODE 1: [B,H,S,D] layout (z selects q/k/v weight set).
// ---------------------------------------------------------------------------
#define KC 32
#define NCH (EE / KC)                 // 24
#define GM_PITCH 80                   // bytes per 32-bf16 row (padded from 64)
#define GM_TILE (128 * GM_PITCH)      // 10240
#define GM_BUF (4 * GM_TILE)          // Ah, Al, Bh, Bl
#define GM_SMEM (3 * GM_BUF)          // 122880

template<int MODE>
__global__ __launch_bounds__(256, 1)
void gemm_mma(const __nv_bfloat16* __restrict__ Ah, const __nv_bfloat16* __restrict__ Al,
              const __nv_bfloat16* __restrict__ Wth, const __nv_bfloat16* __restrict__ Wtl,
              const float* b0, const float* b1, const float* b2, const float* b3,
              float* o0, float* o1, float* o2)
{
    extern __shared__ char smem[];
    const uint32_t sb = smem_u32(smem);
    const int tid = threadIdx.x;
    const int wid = tid >> 5, lane = tid & 31;
    const int wm = wid & 3;          // 4 m-groups of 32 rows
    const int wn = wid >> 2;         // 2 n-groups of 64 cols

    const int wsel = (MODE == 1) ? (int)blockIdx.z : 3;
    const float* bias;
    float* out;
    if (MODE == 1) {
        bias = (wsel == 0) ? b0 : (wsel == 1) ? b1 : b2;
        out  = (wsel == 0) ? o0 : (wsel == 1) ? o1 : o2;
    } else {
        bias = b3; out = o0;
    }
    const __nv_bfloat16* Bh = Wth + (size_t)wsel * EE * EE;
    const __nv_bfloat16* Bl = Wtl + (size_t)wsel * EE * EE;
    const int m0 = blockIdx.y * 128;
    const int n0 = blockIdx.x * 128;

    // chunk loader: 4 tiles (Ah,Al,Bh,Bl), 128 rows x 2 x 16B each
    auto load_chunk = [&](int c) {
        uint32_t buf = sb + (uint32_t)(c % 3) * GM_BUF;
        int k0 = c * KC;
#pragma unroll
        for (int i = 0; i < 2; i++) {
            int idx = tid + i * 256;            // 0..511
            int row = idx >> 2;                 // 0..127
            int j   = idx & 3;                  // 16B quad (j<4 -> k j*8..j*8+7)
            uint32_t off = (uint32_t)(row * GM_PITCH + j * 16);
            size_t ga = (size_t)(m0 + row) * EE + k0 + j * 8;
            size_t gb = (size_t)(n0 + row) * EE + k0 + j * 8;
            cp_async16(buf + 0 * GM_TILE + off, Ah + ga);
            cp_async16(buf + 1 * GM_TILE + off, Al + ga);
            cp_async16(buf + 2 * GM_TILE + off, Bh + gb);
            cp_async16(buf + 3 * GM_TILE + off, Bl + gb);
        }
        cp_commit();
    };

    float acc[2][8][4];
#pragma unroll
    for (int mt = 0; mt < 2; mt++)
#pragma unroll
        for (int nt = 0; nt < 8; nt++)
#pragma unroll
            for (int i = 0; i < 4; i++) acc[mt][nt][i] = 0.f;

    load_chunk(0);
    load_chunk(1);

    const int rA = wm * 32 + (lane & 15);       // ldmatrix A row (local)
    const int rB = wn * 64 + (lane & 15);       // ldmatrix B row (local)
    const uint32_t chalf = (uint32_t)((lane >> 4) * 16);  // k-half byte offset

    for (int c = 0; c < NCH; c++) {
        cp_wait1();            // chunk c resident
        __syncthreads();
        uint32_t buf = sb + (uint32_t)(c % 3) * GM_BUF;

#pragma unroll
        for (int ks = 0; ks < 2; ks++) {
            uint32_t colo = (uint32_t)(ks * 32) + chalf;
            uint32_t ah[2][4], al[2][4], bh[4][4], bl[4][4];
#pragma unroll
            for (int mt = 0; mt < 2; mt++) {
                uint32_t off = (uint32_t)((rA + mt * 16) * GM_PITCH) + colo;
                ldsm_x4(ah[mt], buf + 0 * GM_TILE + off);
                ldsm_x4(al[mt], buf + 1 * GM_TILE + off);
            }
#pragma unroll
            for (int p = 0; p < 4; p++) {
                uint32_t off = (uint32_t)((rB + p * 16) * GM_PITCH) + colo;
                ldsm_x4(bh[p], buf + 2 * GM_TILE + off);
                ldsm_x4(bl[p], buf + 3 * GM_TILE + off);
            }
#pragma unroll
            for (int mt = 0; mt < 2; mt++)
#pragma unroll
                for (int nt = 0; nt < 8; nt++) {
                    const int p = nt >> 1, q = nt & 1;
                    mma16816(acc[mt][nt], ah[mt], bh[p][q], bh[p][q + 2]);
                    mma16816(acc[mt][nt], ah[mt], bl[p][q], bl[p][q + 2]);
                    mma16816(acc[mt][nt], al[mt], bh[p][q], bh[p][q + 2]);
                }
        }

        if (c + 2 < NCH) load_chunk(c + 2);
        else cp_commit();      // keep group counting uniform
    }

    // Epilogue: bias + store fp32.
    // acc[mt][nt] lanes: row = lane/4 (+8 for c2,c3), col = 2*(lane%4)+{0,1}
    const int mrow0 = m0 + wm * 32;
#pragma unroll
    for (int mt = 0; mt < 2; mt++) {
#pragma unroll
        for (int nt = 0; nt < 8; nt++) {
            int ncol = wn * 64 + nt * 8 + 2 * (lane & 3);
            int gn = n0 + ncol;
            float2 bv = *(const float2*)&bias[gn];
            int r0 = mrow0 + mt * 16 + (lane >> 2);
            float2 v0 = { acc[mt][nt][0] + bv.x, acc[mt][nt][1] + bv.y };
            float2 v1 = { acc[mt][nt][2] + bv.x, acc[mt][nt][3] + bv.y };
            if (MODE == 0) {
                *(float2*)&out[(size_t)r0 * EE + gn] = v0;
                *(float2*)&out[(size_t)(r0 + 8) * EE + gn] = v1;
            } else {
                int h = (gn >> 6);
                int d = ncol & 63;
                int b0_ = r0 >> 11, s0 = r0 & (SS - 1);
                int b1_ = (r0 + 8) >> 11, s1 = (r0 + 8) & (SS - 1);
                *(float2*)&out[(((size_t)(b0_ * HH + h)) * SS + s0) * DD + d] = v0;
                *(float2*)&out[(((size_t)(b1_ * HH + h)) * SS + s1) * DD + d] = v1;
            }
        }
    }
}

// ---------------------------------------------------------------------------
// RoPE in-place on q,k in [B,H,S,D] layout.
// ---------------------------------------------------------------------------
__global__ __launch_bounds__(256)
void rope_kernel(float* __restrict__ q, float* __restrict__ k)
{
    int idx = blockIdx.x * blockDim.x + threadIdx.x;
    int i  = idx & 31;
    int s  = (idx >> 5) & (SS - 1);
    int bh = idx >> 16;

    float inv = expf(-(float)i * 0.28782313662425572f);   // ln(10000)/32
    float ang = (float)s * inv;
    float c, sn;
    sincosf(ang, &sn, &c);

    size_t base = ((size_t)bh * SS + s) * DD;
    float* qr = q + base;
    float* kr = k + base;

    float qa = qr[i], qb = qr[i + 32];
    qr[i]      = qa * c - qb * sn;
    qr[i + 32] = qb * c + qa * sn;

    float ka = kr[i], kb = kr[i + 32];
    kr[i]      = ka * c - kb * sn;
    kr[i + 32] = kb * c + ka * sn;
}

// ---------------------------------------------------------------------------
// Flash attention, causal (fp32 SIMT — mma conversion is next round)
// ---------------------------------------------------------------------------
#define ATTN_SMEM_FLOATS (2*64*65 + 64*64)
#define ATTN_SMEM_BYTES  (ATTN_SMEM_FLOATS * 4)

__global__ __launch_bounds__(256)
void attn_kernel(const float* __restrict__ q, const float* __restrict__ k,
                 const float* __restrict__ v, float* __restrict__ out)
{
    extern __shared__ float sm[];
    float (*Qs)[65] = (float(*)[65])sm;
    float (*Ks)[65] = (float(*)[65])(sm + 64 * 65);
    float (*Vs)[64] = (float(*)[64])(sm + 2 * 64 * 65);

    const int mt = blockIdx.x;
    const int bh = blockIdx.y;
    const int m0 = mt * 64;
    const float* qp = q + (size_t)bh * SS * DD;
    const float* kp = k + (size_t)bh * SS * DD;
    const float* vp = v + (size_t)bh * SS * DD;

    const int tid = threadIdx.x;
    const int tx = tid & 15;
    const int ty = tid >> 4;

#pragma unroll
    for (int i = 0; i < 4; i++) {
        int idx = tid + i * 256;
        int r  = idx >> 4;
        int d4 = (idx & 15) * 4;
        float4 a = *(const float4*)&qp[(size_t)(m0 + r) * DD + d4];
        Qs[d4 + 0][r] = a.x;
        Qs[d4 + 1][r] = a.y;
        Qs[d4 + 2][r] = a.z;
        Qs[d4 + 3][r] = a.w;
    }

    float mi[4], li[4], acc[4][4];
#pragma unroll
    for (int r = 0; r < 4; r++) {
        mi[r] = -1e30f; li[r] = 0.f;
#pragma unroll
        for (int c = 0; c < 4; c++) acc[r][c] = 0.f;
    }

    for (int nt = 0; nt <= mt; nt++) {
        __syncthreads();
        int n0 = nt * 64;
#pragma unroll
        for (int i = 0; i < 4; i++) {
            int idx = tid + i * 256;
            int r  = idx >> 4;
            int d4 = (idx & 15) * 4;
            float4 a = *(const float4*)&kp[(size_t)(n0 + r) * DD + d4];
            Ks[d4 + 0][r] = a.x;
            Ks[d4 + 1][r] = a.y;
            Ks[d4 + 2][r] = a.z;
            Ks[d4 + 3][r] = a.w;
            float4 b = *(const float4*)&vp[(size_t)(n0 + r) * DD + d4];
            *(float4*)&Vs[r][d4] = b;
        }
        __syncthreads();

        float sc[4][4];
#pragma unroll
        for (int r = 0; r < 4; r++)
#pragma unroll
            for (int c = 0; c < 4; c++) sc[r][c] = 0.f;

#pragma unroll 8
        for (int d = 0; d < 64; d++) {
            float qv[4], kv[4];
#pragma unroll
            for (int r = 0; r < 4; r++) qv[r] = Qs[d][ty * 4 + r];
#pragma unroll
            for (int c = 0; c < 4; c++) kv[c] = Ks[d][tx * 4 + c];
#pragma unroll
            for (int r = 0; r < 4; r++)
#pragma unroll
                for (int c = 0; c < 4; c++)
                    sc[r][c] = fmaf(qv[r], kv[c], sc[r][c]);
        }

#pragma unroll
        for (int r = 0; r < 4; r++)
#pragma unroll
            for (int c = 0; c < 4; c++) {
                sc[r][c] *= 0.125f;
                if (nt == mt && (tx * 4 + c) > (ty * 4 + r)) sc[r][c] = -1e30f;
            }

#pragma unroll
        for (int r = 0; r < 4; r++) {
            float tm = sc[r][0];
#pragma unroll
            for (int c = 1; c < 4; c++) tm = fmaxf(tm, sc[r][c]);
#pragma unroll
            for (int msk = 8; msk >= 1; msk >>= 1)
                tm = fmaxf(tm, __shfl_xor_sync(0xffffffffu, tm, msk));
            float mn = fmaxf(mi[r], tm);
            float alpha = expf(mi[r] - mn);
            float rs = 0.f;
#pragma unroll
            for (int c = 0; c < 4; c++) {
                float p = expf(sc[r][c] - mn);
                sc[r][c] = p;
                rs += p;
            }
#pragma unroll
            for (int msk = 8; msk >= 1; msk >>= 1)
                rs += __shfl_xor_sync(0xffffffffu, rs, msk);
            li[r] = li[r] * alpha + rs;
            mi[r] = mn;
#pragma unroll
            for (int c = 0; c < 4; c++) acc[r][c] *= alpha;
        }

        __syncthreads();
#pragma unroll
        for (int r = 0; r < 4; r++)
#pragma unroll
            for (int c = 0; c < 4; c++)
                Ks[tx * 4 + c][ty * 4 + r] = sc[r][c];
        __syncthreads();

#pragma unroll 8
        for (int n = 0; n < 64; n++) {
            float pv[4], vv[4];
#pragma unroll
            for (int r = 0; r < 4; r++) pv[r] = Ks[n][ty * 4 + r];
#pragma unroll
            for (int c = 0; c < 4; c++) vv[c] = Vs[n][tx * 4 + c];
#pragma unroll
            for (int r = 0; r < 4; r++)
#pragma unroll
                for (int c = 0; c < 4; c++)
                    acc[r][c] = fmaf(pv[r], vv[c], acc[r][c]);
        }
    }

    const int b_ = bh / HH;
    const int h  = bh % HH;
#pragma unroll
    for (int r = 0; r < 4; r++) {
        float invl = 1.f / li[r];
        int m = m0 + ty * 4 + r;
#pragma unroll
        for (int c = 0; c < 4; c++)
            out[((size_t)(b_ * SS + m)) * EE + h * DD + tx * 4 + c] = acc[r][c] * invl;
    }
}

// ---------------------------------------------------------------------------
extern "C" void kernel_launch(void* const* d_in, const int* in_sizes, int n_in,
                              void* d_out, int out_size)
{
    (void)in_sizes; (void)n_in; (void)out_size;
    const float* x  = (const float*)d_in[0];
    const float* Wq = (const float*)d_in[1];
    const float* bq = (const float*)d_in[2];
    const float* Wk = (const float*)d_in[3];
    const float* bk = (const float*)d_in[4];
    const float* Wv = (const float*)d_in[5];
    const float* bv = (const float*)d_in[6];
    const float* Wp = (const float*)d_in[7];
    const float* bp = (const float*)d_in[8];

    float *q, *k, *v, *attn;
    __nv_bfloat16 *ah, *al, *wth, *wtl;
    cudaGetSymbolAddress((void**)&q,    g_q);
    cudaGetSymbolAddress((void**)&k,    g_k);
    cudaGetSymbolAddress((void**)&v,    g_v);
    cudaGetSymbolAddress((void**)&attn, g_attn);
    cudaGetSymbolAddress((void**)&ah,   g_ah);
    cudaGetSymbolAddress((void**)&al,   g_al);
    cudaGetSymbolAddress((void**)&wth,  g_wth);
    cudaGetSymbolAddress((void**)&wtl,  g_wtl);

    cudaFuncSetAttribute(attn_kernel,
                         cudaFuncAttributeMaxDynamicSharedMemorySize, ATTN_SMEM_BYTES);
    cudaFuncSetAttribute(gemm_mma<1>,
                         cudaFuncAttributeMaxDynamicSharedMemorySize, GM_SMEM);
    cudaFuncSetAttribute(gemm_mma<0>,
                         cudaFuncAttributeMaxDynamicSharedMemorySize, GM_SMEM);

    // Split x and all 4 weight matrices into bf16 hi/lo (weights transposed)
    split_convert<<<(MT * EE + 255) / 256, 256>>>(x, ah, al, MT * EE);
    transpose_split<<<dim3(EE / 32, EE / 32, 4), 256>>>(Wq, Wk, Wv, Wp, wth, wtl);

    // Fused Q/K/V projections via mma.sync (z selects weight set) -> [B,H,S,D]
    gemm_mma<1><<<dim3(EE / 128, MT / 128, 3), 256, GM_SMEM>>>(
        ah, al, wth, wtl, bq, bk, bv, nullptr, q, k, v);

    // RoPE in place on q,k
    rope_kernel<<<(BB * HH * SS * 32) / 256, 256>>>(q, k);

    // Causal flash attention -> g_attn [B,S,E]
    attn_kernel<<<dim3(SS / 64, BB * HH), 256, ATTN_SMEM_BYTES>>>(q, k, v, attn);

    // Split attention output, then output projection -> d_out
    split_convert<<<(MT * EE + 255) / 256, 256>>>(attn, ah, al, MT * EE);
    gemm_mma<0><<<dim3(EE / 128, MT / 128, 1), 256, GM_SMEM>>>(
        ah, al, wth, wtl, nullptr, nullptr, nullptr, bp,
        (float*)d_out, nullptr, nullptr);
}

// round 7
// speedup vs baseline: 2.5453x; 1.9819x over previous
#include <cuda_runtime.h>
#include <cuda_bf16.h>
#include <math.h>
#include <stdint.h>

#define BB 2
#define SS 2048
#define EE 768
#define HH 12
#define DD 64
#define MT (BB*SS)

// ---------------------------------------------------------------------------
// Scratch (allocation-free rule: __device__ globals)
// ---------------------------------------------------------------------------
__device__ float g_q[(size_t)BB*HH*SS*DD];
__device__ float g_k[(size_t)BB*HH*SS*DD];
__device__ float g_v[(size_t)BB*HH*SS*DD];
__device__ __nv_bfloat16 g_ah[(size_t)MT*EE];
__device__ __nv_bfloat16 g_al[(size_t)MT*EE];
__device__ __nv_bfloat16 g_wth[(size_t)4*EE*EE];   // [4][n][k] = W[k][n] hi
__device__ __nv_bfloat16 g_wtl[(size_t)4*EE*EE];   // lo
__device__ __nv_bfloat16 g_qh[(size_t)BB*HH*SS*DD];
__device__ __nv_bfloat16 g_ql[(size_t)BB*HH*SS*DD];
__device__ __nv_bfloat16 g_kh[(size_t)BB*HH*SS*DD];
__device__ __nv_bfloat16 g_kl[(size_t)BB*HH*SS*DD];
__device__ __nv_bfloat16 g_vh[(size_t)BB*HH*SS*DD];
__device__ __nv_bfloat16 g_vl[(size_t)BB*HH*SS*DD];

// ---------------------------------------------------------------------------
// PTX helpers (BASE ISA ONLY — harness ptxas targets sm_103 without 'a')
// ---------------------------------------------------------------------------
__device__ __forceinline__ uint32_t smem_u32(const void* p) {
    uint32_t a;
    asm("{ .reg .u64 t; cvta.to.shared.u64 t, %1; cvt.u32.u64 %0, t; }"
        : "=r"(a) : "l"(p));
    return a;
}
__device__ __forceinline__ void cp_async16(uint32_t saddr, const void* gaddr) {
    asm volatile("cp.async.cg.shared.global [%0], [%1], 16;"
                 :: "r"(saddr), "l"(gaddr) : "memory");
}
__device__ __forceinline__ void cp_commit() {
    asm volatile("cp.async.commit_group;" ::: "memory");
}
__device__ __forceinline__ void cp_wait1() {
    asm volatile("cp.async.wait_group 1;" ::: "memory");
}
__device__ __forceinline__ void ldsm_x4(uint32_t* r, uint32_t addr) {
    asm volatile("ldmatrix.sync.aligned.m8n8.x4.shared.b16 {%0,%1,%2,%3}, [%4];"
                 : "=r"(r[0]), "=r"(r[1]), "=r"(r[2]), "=r"(r[3]) : "r"(addr));
}
__device__ __forceinline__ void ldsm_x4_t(uint32_t* r, uint32_t addr) {
    asm volatile("ldmatrix.sync.aligned.m8n8.x4.trans.shared.b16 {%0,%1,%2,%3}, [%4];"
                 : "=r"(r[0]), "=r"(r[1]), "=r"(r[2]), "=r"(r[3]) : "r"(addr));
}
__device__ __forceinline__ void mma16816(float* c, const uint32_t* a,
                                         uint32_t b0, uint32_t b1) {
    asm volatile(
        "mma.sync.aligned.m16n8k16.row.col.f32.bf16.bf16.f32 "
        "{%0,%1,%2,%3}, {%4,%5,%6,%7}, {%8,%9}, {%0,%1,%2,%3};"
        : "+f"(c[0]), "+f"(c[1]), "+f"(c[2]), "+f"(c[3])
        : "r"(a[0]), "r"(a[1]), "r"(a[2]), "r"(a[3]), "r"(b0), "r"(b1));
}
// split (p0,p1) into packed bf16 hi and bf16 lo (residual) registers
__device__ __forceinline__ void psplit(float p0, float p1,
                                       uint32_t& hreg, uint32_t& lreg) {
    __nv_bfloat162 hh = __float22bfloat162_rn(make_float2(p0, p1));
    float r0 = p0 - __bfloat162float(hh.x);
    float r1 = p1 - __bfloat162float(hh.y);
    __nv_bfloat162 ll = __float22bfloat162_rn(make_float2(r0, r1));
    hreg = *reinterpret_cast<uint32_t*>(&hh);
    lreg = *reinterpret_cast<uint32_t*>(&ll);
}
__device__ __forceinline__ void fsplit(float x, __nv_bfloat16& h, __nv_bfloat16& l) {
    h = __float2bfloat16(x);
    l = __float2bfloat16(x - __bfloat162float(h));
}

// ---------------------------------------------------------------------------
// Precision-split conversion: x -> (bf16 hi, bf16 lo)
// ---------------------------------------------------------------------------
__global__ __launch_bounds__(256)
void split_convert(const float* __restrict__ in, __nv_bfloat16* __restrict__ h,
                   __nv_bfloat16* __restrict__ l, int n)
{
    int i = blockIdx.x * blockDim.x + threadIdx.x;
    if (i < n) {
        float x = in[i];
        __nv_bfloat16 hi, lo;
        fsplit(x, hi, lo);
        h[i] = hi;
        l[i] = lo;
    }
}

// Transpose + split: Wt[z][n][k] = W_z[k][n]  (hi/lo bf16)
__global__ __launch_bounds__(256)
void transpose_split(const float* __restrict__ W0, const float* __restrict__ W1,
                     const float* __restrict__ W2, const float* __restrict__ W3,
                     __nv_bfloat16* __restrict__ th, __nv_bfloat16* __restrict__ tl)
{
    __shared__ float t[32][33];
    const float* W = (blockIdx.z == 0) ? W0 : (blockIdx.z == 1) ? W1
                   : (blockIdx.z == 2) ? W2 : W3;
    int n0 = blockIdx.x * 32, k0 = blockIdx.y * 32;
    int tx = threadIdx.x & 31, ty = threadIdx.x >> 5;
#pragma unroll
    for (int i = 0; i < 4; i++)
        t[ty + 8 * i][tx] = W[(size_t)(k0 + ty + 8 * i) * EE + n0 + tx];
    __syncthreads();
    size_t base = (size_t)blockIdx.z * EE * EE;
#pragma unroll
    for (int i = 0; i < 4; i++) {
        int row = ty + 8 * i;                 // local n
        float x = t[tx][row];                 // = W[k0+tx][n0+row]
        __nv_bfloat16 hi, lo;
        fsplit(x, hi, lo);
        size_t o = base + (size_t)(n0 + row) * EE + k0 + tx;
        th[o] = hi;
        tl[o] = lo;
    }
}

// ---------------------------------------------------------------------------
// mma.sync GEMM: C[M,768] = A[M,768] @ W[768,768] + bias  (bf16x3 split)
// CTA 128x128, 8 warps of 32x64, K-chunk 32, 2-stage cp.async, occupancy 2.
// MODE 0: C[m*EE+n].  MODE 1: [B,H,S,D] layout (z selects q/k/v weight set).
// ---------------------------------------------------------------------------
#define KC 32
#define NCH (EE / KC)                 // 24
#define GM_PITCH 80                   // bytes per 32-bf16 row (padded from 64)
#define GM_TILE (128 * GM_PITCH)      // 10240
#define GM_BUF (4 * GM_TILE)          // Ah, Al, Bh, Bl
#define GM_SMEM (2 * GM_BUF)          // 81920 -> 2 CTAs/SM

template<int MODE>
__global__ __launch_bounds__(256, 2)
void gemm_mma(const __nv_bfloat16* __restrict__ Ah, const __nv_bfloat16* __restrict__ Al,
              const __nv_bfloat16* __restrict__ Wth, const __nv_bfloat16* __restrict__ Wtl,
              const float* b0, const float* b1, const float* b2, const float* b3,
              float* o0, float* o1, float* o2)
{
    extern __shared__ char smem[];
    const uint32_t sb = smem_u32(smem);
    const int tid = threadIdx.x;
    const int wid = tid >> 5, lane = tid & 31;
    const int wm = wid & 3;          // 4 m-groups of 32 rows
    const int wn = wid >> 2;         // 2 n-groups of 64 cols

    const int wsel = (MODE == 1) ? (int)blockIdx.z : 3;
    const float* bias;
    float* out;
    if (MODE == 1) {
        bias = (wsel == 0) ? b0 : (wsel == 1) ? b1 : b2;
        out  = (wsel == 0) ? o0 : (wsel == 1) ? o1 : o2;
    } else {
        bias = b3; out = o0;
    }
    const __nv_bfloat16* Bh = Wth + (size_t)wsel * EE * EE;
    const __nv_bfloat16* Bl = Wtl + (size_t)wsel * EE * EE;
    const int m0 = blockIdx.y * 128;
    const int n0 = blockIdx.x * 128;

    auto load_chunk = [&](int c) {
        uint32_t buf = sb + (uint32_t)(c & 1) * GM_BUF;
        int k0 = c * KC;
#pragma unroll
        for (int i = 0; i < 2; i++) {
            int idx = tid + i * 256;            // 0..511
            int row = idx >> 2;                 // 0..127
            int j   = idx & 3;                  // 16B quad
            uint32_t off = (uint32_t)(row * GM_PITCH + j * 16);
            size_t ga = (size_t)(m0 + row) * EE + k0 + j * 8;
            size_t gb = (size_t)(n0 + row) * EE + k0 + j * 8;
            cp_async16(buf + 0 * GM_TILE + off, Ah + ga);
            cp_async16(buf + 1 * GM_TILE + off, Al + ga);
            cp_async16(buf + 2 * GM_TILE + off, Bh + gb);
            cp_async16(buf + 3 * GM_TILE + off, Bl + gb);
        }
        cp_commit();
    };

    float acc[2][8][4];
#pragma unroll
    for (int mt = 0; mt < 2; mt++)
#pragma unroll
        for (int nt = 0; nt < 8; nt++)
#pragma unroll
            for (int i = 0; i < 4; i++) acc[mt][nt][i] = 0.f;

    load_chunk(0);
    load_chunk(1);

    const int rA = wm * 32 + (lane & 15);
    const int rB = wn * 64 + (lane & 15);
    const uint32_t chalf = (uint32_t)((lane >> 4) * 16);

    for (int c = 0; c < NCH; c++) {
        cp_wait1();            // chunk c resident
        __syncthreads();
        uint32_t buf = sb + (uint32_t)(c & 1) * GM_BUF;

#pragma unroll
        for (int ks = 0; ks < 2; ks++) {
            uint32_t colo = (uint32_t)(ks * 32) + chalf;
            uint32_t ah[2][4], al[2][4], bh[4][4], bl[4][4];
#pragma unroll
            for (int mt = 0; mt < 2; mt++) {
                uint32_t off = (uint32_t)((rA + mt * 16) * GM_PITCH) + colo;
                ldsm_x4(ah[mt], buf + 0 * GM_TILE + off);
                ldsm_x4(al[mt], buf + 1 * GM_TILE + off);
            }
#pragma unroll
            for (int p = 0; p < 4; p++) {
                uint32_t off = (uint32_t)((rB + p * 16) * GM_PITCH) + colo;
                ldsm_x4(bh[p], buf + 2 * GM_TILE + off);
                ldsm_x4(bl[p], buf + 3 * GM_TILE + off);
            }
#pragma unroll
            for (int mt = 0; mt < 2; mt++)
#pragma unroll
                for (int nt = 0; nt < 8; nt++) {
                    const int p = nt >> 1, q = nt & 1;
                    mma16816(acc[mt][nt], ah[mt], bh[p][q], bh[p][q + 2]);
                    mma16816(acc[mt][nt], ah[mt], bl[p][q], bl[p][q + 2]);
                    mma16816(acc[mt][nt], al[mt], bh[p][q], bh[p][q + 2]);
                }
        }

        __syncthreads();       // all warps done reading slot c&1
        if (c + 2 < NCH) load_chunk(c + 2);
        else cp_commit();
    }

    const int mrow0 = m0 + wm * 32;
#pragma unroll
    for (int mt = 0; mt < 2; mt++) {
#pragma unroll
        for (int nt = 0; nt < 8; nt++) {
            int ncol = wn * 64 + nt * 8 + 2 * (lane & 3);
            int gn = n0 + ncol;
            float2 bv = *(const float2*)&bias[gn];
            int r0 = mrow0 + mt * 16 + (lane >> 2);
            float2 v0 = { acc[mt][nt][0] + bv.x, acc[mt][nt][1] + bv.y };
            float2 v1 = { acc[mt][nt][2] + bv.x, acc[mt][nt][3] + bv.y };
            if (MODE == 0) {
                *(float2*)&out[(size_t)r0 * EE + gn] = v0;
                *(float2*)&out[(size_t)(r0 + 8) * EE + gn] = v1;
            } else {
                int h = (gn >> 6);
                int d = ncol & 63;
                int b0_ = r0 >> 11, s0 = r0 & (SS - 1);
                int b1_ = (r0 + 8) >> 11, s1 = (r0 + 8) & (SS - 1);
                *(float2*)&out[(((size_t)(b0_ * HH + h)) * SS + s0) * DD + d] = v0;
                *(float2*)&out[(((size_t)(b1_ * HH + h)) * SS + s1) * DD + d] = v1;
            }
        }
    }
}

// ---------------------------------------------------------------------------
// RoPE + split: read fp32 q,k [B,H,S,D], write bf16 hi/lo.
// Q is pre-scaled by 1/sqrt(D)=0.125 so attention needs no score scaling.
// ---------------------------------------------------------------------------
__global__ __launch_bounds__(256)
void rope_split(const float* __restrict__ q, const float* __restrict__ k,
                __nv_bfloat16* __restrict__ qh, __nv_bfloat16* __restrict__ ql,
                __nv_bfloat16* __restrict__ kh, __nv_bfloat16* __restrict__ kl)
{
    int idx = blockIdx.x * blockDim.x + threadIdx.x;
    int i  = idx & 31;
    int s  = (idx >> 5) & (SS - 1);
    int bh = idx >> 16;

    float inv = expf(-(float)i * 0.28782313662425572f);   // ln(10000)/32
    float ang = (float)s * inv;
    float c, sn;
    sincosf(ang, &sn, &c);

    size_t base = ((size_t)bh * SS + s) * DD;
    const float* qr = q + base;
    const float* kr = k + base;

    float qa = qr[i], qb = qr[i + 32];
    float q0 = (qa * c - qb * sn) * 0.125f;
    float q1 = (qb * c + qa * sn) * 0.125f;
    float ka = kr[i], kb = kr[i + 32];
    float k0 = ka * c - kb * sn;
    float k1 = kb * c + ka * sn;

    __nv_bfloat16 h, l;
    fsplit(q0, h, l); qh[base + i] = h;      ql[base + i] = l;
    fsplit(q1, h, l); qh[base + i + 32] = h; ql[base + i + 32] = l;
    fsplit(k0, h, l); kh[base + i] = h;      kl[base + i] = l;
    fsplit(k1, h, l); kh[base + i + 32] = h; kl[base + i + 32] = l;
}

// ---------------------------------------------------------------------------
// Tensor-core causal flash attention (bf16x3 split, mma.sync).
// CTA = 128 Q rows x one (b,h); 8 warps x 16 rows each (softmax warp-local).
// K/V tiles of 64 double-buffered via cp.async. V consumed via ldmatrix.trans.
// Output written directly as split bf16 (feeds the output-projection GEMM).
// ---------------------------------------------------------------------------
#define AT_PITCH 144                      // 64 bf16 = 128B data + 16B pad
#define AT_Q (128 * AT_PITCH)             // 18432 per Q tile (hi or lo)
#define AT_KV (64 * AT_PITCH)             // 9216 per K/V tile
#define AT_STAGE (4 * AT_KV)              // Kh,Kl,Vh,Vl = 36864
#define AT_SMEM (2 * AT_Q + 2 * AT_STAGE) // 110592

__global__ __launch_bounds__(256, 1)
void attn_mma(const __nv_bfloat16* __restrict__ qh, const __nv_bfloat16* __restrict__ ql,
              const __nv_bfloat16* __restrict__ kh, const __nv_bfloat16* __restrict__ kl,
              const __nv_bfloat16* __restrict__ vh, const __nv_bfloat16* __restrict__ vl,
              __nv_bfloat16* __restrict__ oh, __nv_bfloat16* __restrict__ ol)
{
    extern __shared__ char smem[];
    const uint32_t sb = smem_u32(smem);
    const int tid = threadIdx.x;
    const int wid = tid >> 5, lane = tid & 31;

    const int mtile = (int)(gridDim.x - 1 - blockIdx.x);   // heavy CTAs first
    const int bh = blockIdx.y;
    const int m0 = mtile * 128;
    const int ntmax = 2 * mtile + 1;
    const size_t hbase = (size_t)bh * SS * DD;
    const __nv_bfloat16* qhp = qh + hbase;
    const __nv_bfloat16* qlp = ql + hbase;
    const __nv_bfloat16* khp = kh + hbase;
    const __nv_bfloat16* klp = kl + hbase;
    const __nv_bfloat16* vhp = vh + hbase;
    const __nv_bfloat16* vlp = vl + hbase;

    // ---- load Q tile (hi+lo) ----
#pragma unroll
    for (int i = 0; i < 4; i++) {
        int cid = tid + i * 256;           // 0..1023
        int row = cid >> 3;
        int j   = cid & 7;
        uint32_t off = (uint32_t)(row * AT_PITCH + j * 16);
        size_t g = (size_t)(m0 + row) * DD + j * 8;
        cp_async16(sb + off, qhp + g);
        cp_async16(sb + AT_Q + off, qlp + g);
    }
    cp_commit();

    auto load_kv = [&](int t) {
        if (t <= ntmax) {
            uint32_t base = sb + 2 * AT_Q + (uint32_t)(t & 1) * AT_STAGE;
            int n0 = t * 64;
#pragma unroll
            for (int i = 0; i < 2; i++) {
                int cid = tid + i * 256;       // 0..511
                int row = cid >> 3;
                int j   = cid & 7;
                uint32_t off = (uint32_t)(row * AT_PITCH + j * 16);
                size_t g = (size_t)(n0 + row) * DD + j * 8;
                cp_async16(base + 0 * AT_KV + off, khp + g);
                cp_async16(base + 1 * AT_KV + off, klp + g);
                cp_async16(base + 2 * AT_KV + off, vhp + g);
                cp_async16(base + 3 * AT_KV + off, vlp + g);
            }
        }
        cp_commit();
    };
    load_kv(0);
    load_kv(1);

    float oacc[8][4];
#pragma unroll
    for (int d = 0; d < 8; d++)
#pragma unroll
        for (int j = 0; j < 4; j++) oacc[d][j] = 0.f;
    float mi0 = -1e30f, mi1 = -1e30f, li0 = 0.f, li1 = 0.f;
    uint32_t qfh[4][4], qfl[4][4];

    const int wr0 = m0 + wid * 16;     // warp's first global Q row

    for (int nt = 0; nt <= ntmax; nt++) {
        cp_wait1();
        __syncthreads();               // stage nt (and Q at nt=0) visible

        if (nt == 0) {                 // load Q fragments once
#pragma unroll
            for (int kc = 0; kc < 4; kc++) {
                uint32_t a = sb + (uint32_t)((wid * 16 + (lane & 15)) * AT_PITCH)
                           + (uint32_t)(kc * 32) + (uint32_t)((lane >> 4) * 16);
                ldsm_x4(qfh[kc], a);
                ldsm_x4(qfl[kc], a + AT_Q);
            }
        }

        const int n0 = nt * 64;
        if (n0 <= wr0 + 15) {          // warp has unmasked rows in this tile
            const uint32_t kvb = sb + 2 * AT_Q + (uint32_t)(nt & 1) * AT_STAGE;

            // ---- S = Q K^T (3-term split) ----
            float sacc[8][4];
#pragma unroll
            for (int t8 = 0; t8 < 8; t8++)
#pragma unroll
                for (int j = 0; j < 4; j++) sacc[t8][j] = 0.f;

#pragma unroll
            for (int kc = 0; kc < 4; kc++) {
                uint32_t colo = (uint32_t)(kc * 32) + (uint32_t)((lane >> 4) * 16);
#pragma unroll
                for (int st = 0; st < 4; st++) {
                    uint32_t a = kvb + (uint32_t)((st * 16 + (lane & 15)) * AT_PITCH) + colo;
                    uint32_t k4h[4], k4l[4];
                    ldsm_x4(k4h, a);
                    ldsm_x4(k4l, a + AT_KV);
                    mma16816(sacc[2 * st],     qfh[kc], k4h[0], k4h[2]);
                    mma16816(sacc[2 * st],     qfh[kc], k4l[0], k4l[2]);
                    mma16816(sacc[2 * st],     qfl[kc], k4h[0], k4h[2]);
                    mma16816(sacc[2 * st + 1], qfh[kc], k4h[1], k4h[3]);
                    mma16816(sacc[2 * st + 1], qfh[kc], k4l[1], k4l[3]);
                    mma16816(sacc[2 * st + 1], qfl[kc], k4h[1], k4h[3]);
                }
            }

            // ---- causal mask (diagonal tiles only) ----
            const int rr0 = wr0 + (lane >> 2);
            if (n0 + 63 > wr0) {
#pragma unroll
                for (int t8 = 0; t8 < 8; t8++) {
                    int c0 = n0 + t8 * 8 + 2 * (lane & 3);
                    if (c0     > rr0)     sacc[t8][0] = -1e30f;
                    if (c0 + 1 > rr0)     sacc[t8][1] = -1e30f;
                    if (c0     > rr0 + 8) sacc[t8][2] = -1e30f;
                    if (c0 + 1 > rr0 + 8) sacc[t8][3] = -1e30f;
                }
            }

            // ---- online softmax (rows lane/4 and lane/4+8) ----
            float mx0 = -1e30f, mx1 = -1e30f;
#pragma unroll
            for (int t8 = 0; t8 < 8; t8++) {
                mx0 = fmaxf(mx0, fmaxf(sacc[t8][0], sacc[t8][1]));
                mx1 = fmaxf(mx1, fmaxf(sacc[t8][2], sacc[t8][3]));
            }
            mx0 = fmaxf(mx0, __shfl_xor_sync(0xffffffffu, mx0, 1));
            mx0 = fmaxf(mx0, __shfl_xor_sync(0xffffffffu, mx0, 2));
            mx1 = fmaxf(mx1, __shfl_xor_sync(0xffffffffu, mx1, 1));
            mx1 = fmaxf(mx1, __shfl_xor_sync(0xffffffffu, mx1, 2));
            float mn0 = fmaxf(mi0, mx0), mn1 = fmaxf(mi1, mx1);
            float al0 = __expf(mi0 - mn0), al1 = __expf(mi1 - mn1);
            mi0 = mn0; mi1 = mn1;
            float s0 = 0.f, s1 = 0.f;
#pragma unroll
            for (int t8 = 0; t8 < 8; t8++) {
                float p0 = __expf(sacc[t8][0] - mn0);
                float p1 = __expf(sacc[t8][1] - mn0);
                float p2 = __expf(sacc[t8][2] - mn1);
                float p3 = __expf(sacc[t8][3] - mn1);
                sacc[t8][0] = p0; sacc[t8][1] = p1;
                sacc[t8][2] = p2; sacc[t8][3] = p3;
                s0 += p0 + p1; s1 += p2 + p3;
            }
            li0 = li0 * al0 + s0;        // lane-partial row sums
            li1 = li1 * al1 + s1;
#pragma unroll
            for (int d = 0; d < 8; d++) {
                oacc[d][0] *= al0; oacc[d][1] *= al0;
                oacc[d][2] *= al1; oacc[d][3] *= al1;
            }

            // ---- P -> bf16 hi/lo A-fragments (S-frag layout == A-frag layout) ----
            uint32_t aPh[4][4], aPl[4][4];
#pragma unroll
            for (int kc = 0; kc < 4; kc++) {
                psplit(sacc[2 * kc][0],     sacc[2 * kc][1],     aPh[kc][0], aPl[kc][0]);
                psplit(sacc[2 * kc][2],     sacc[2 * kc][3],     aPh[kc][1], aPl[kc][1]);
                psplit(sacc[2 * kc + 1][0], sacc[2 * kc + 1][1], aPh[kc][2], aPl[kc][2]);
                psplit(sacc[2 * kc + 1][2], sacc[2 * kc + 1][3], aPh[kc][3], aPl[kc][3]);
            }

            // ---- O += P V (3-term split, V via ldmatrix.trans) ----
            const uint32_t vbb = kvb + 2 * AT_KV;
#pragma unroll
            for (int kc = 0; kc < 4; kc++) {
#pragma unroll
                for (int vp = 0; vp < 4; vp++) {
                    uint32_t a = vbb + (uint32_t)((kc * 16 + (lane & 15)) * AT_PITCH)
                               + (uint32_t)(vp * 32) + (uint32_t)((lane >> 4) * 16);
                    uint32_t v4h[4], v4l[4];
                    ldsm_x4_t(v4h, a);
                    ldsm_x4_t(v4l, a + AT_KV);
                    mma16816(oacc[2 * vp],     aPh[kc], v4h[0], v4h[1]);
                    mma16816(oacc[2 * vp],     aPl[kc], v4h[0], v4h[1]);
                    mma16816(oacc[2 * vp],     aPh[kc], v4l[0], v4l[1]);
                    mma16816(oacc[2 * vp + 1], aPh[kc], v4h[2], v4h[3]);
                    mma16816(oacc[2 * vp + 1], aPl[kc], v4h[2], v4h[3]);
                    mma16816(oacc[2 * vp + 1], aPh[kc], v4l[2], v4l[3]);
                }
            }
        }

        __syncthreads();               // all warps done reading slot nt&1
        load_kv(nt + 2);
    }

    // ---- normalize + write split bf16 output [m][E] at cols h*64.. ----
    li0 += __shfl_xor_sync(0xffffffffu, li0, 1);
    li0 += __shfl_xor_sync(0xffffffffu, li0, 2);
    li1 += __shfl_xor_sync(0xffffffffu, li1, 1);
    li1 += __shfl_xor_sync(0xffffffffu, li1, 2);
    const float inv0 = 1.f / li0, inv1 = 1.f / li1;

    const int b_ = bh / HH, h_ = bh % HH;
    const int r0g = m0 + wid * 16 + (lane >> 2);
#pragma unroll
    for (int dt = 0; dt < 8; dt++) {
        int col = h_ * 64 + dt * 8 + 2 * (lane & 3);
        size_t o0 = (size_t)(b_ * SS + r0g) * EE + col;
        size_t o1 = (size_t)(b_ * SS + r0g + 8) * EE + col;
        uint32_t hreg, lreg;
        psplit(oacc[dt][0] * inv0, oacc[dt][1] * inv0, hreg, lreg);
        *(uint32_t*)&oh[o0] = hreg;
        *(uint32_t*)&ol[o0] = lreg;
        psplit(oacc[dt][2] * inv1, oacc[dt][3] * inv1, hreg, lreg);
        *(uint32_t*)&oh[o1] = hreg;
        *(uint32_t*)&ol[o1] = lreg;
    }
}

// ---------------------------------------------------------------------------
extern "C" void kernel_launch(void* const* d_in, const int* in_sizes, int n_in,
                              void* d_out, int out_size)
{
    (void)in_sizes; (void)n_in; (void)out_size;
    const float* x  = (const float*)d_in[0];
    const float* Wq = (const float*)d_in[1];
    const float* bq = (const float*)d_in[2];
    const float* Wk = (const float*)d_in[3];
    const float* bk = (const float*)d_in[4];
    const float* Wv = (const float*)d_in[5];
    const float* bv = (const float*)d_in[6];
    const float* Wp = (const float*)d_in[7];
    const float* bp = (const float*)d_in[8];

    float *q, *k, *v;
    __nv_bfloat16 *ah, *al, *wth, *wtl, *qh, *ql, *kh, *kl, *vh, *vl;
    cudaGetSymbolAddress((void**)&q,   g_q);
    cudaGetSymbolAddress((void**)&k,   g_k);
    cudaGetSymbolAddress((void**)&v,   g_v);
    cudaGetSymbolAddress((void**)&ah,  g_ah);
    cudaGetSymbolAddress((void**)&al,  g_al);
    cudaGetSymbolAddress((void**)&wth, g_wth);
    cudaGetSymbolAddress((void**)&wtl, g_wtl);
    cudaGetSymbolAddress((void**)&qh,  g_qh);
    cudaGetSymbolAddress((void**)&ql,  g_ql);
    cudaGetSymbolAddress((void**)&kh,  g_kh);
    cudaGetSymbolAddress((void**)&kl,  g_kl);
    cudaGetSymbolAddress((void**)&vh,  g_vh);
    cudaGetSymbolAddress((void**)&vl,  g_vl);

    cudaFuncSetAttribute(gemm_mma<1>,
                         cudaFuncAttributeMaxDynamicSharedMemorySize, GM_SMEM);
    cudaFuncSetAttribute(gemm_mma<0>,
                         cudaFuncAttributeMaxDynamicSharedMemorySize, GM_SMEM);
    cudaFuncSetAttribute(attn_mma,
                         cudaFuncAttributeMaxDynamicSharedMemorySize, AT_SMEM);

    // Split x and all 4 weight matrices into bf16 hi/lo (weights transposed)
    split_convert<<<(MT * EE + 255) / 256, 256>>>(x, ah, al, MT * EE);
    transpose_split<<<dim3(EE / 32, EE / 32, 4), 256>>>(Wq, Wk, Wv, Wp, wth, wtl);

    // Fused Q/K/V projections -> fp32 [B,H,S,D]
    gemm_mma<1><<<dim3(EE / 128, MT / 128, 3), 256, GM_SMEM>>>(
        ah, al, wth, wtl, bq, bk, bv, nullptr, q, k, v);

    // RoPE + split (Q pre-scaled by 0.125); split V
    rope_split<<<(BB * HH * SS * 32) / 256, 256>>>(q, k, qh, ql, kh, kl);
    split_convert<<<(BB * HH * SS * DD + 255) / 256, 256>>>(v, vh, vl,
                                                            BB * HH * SS * DD);

    // Tensor-core causal flash attention -> split bf16 [B,S,E] (into ah/al)
    attn_mma<<<dim3(SS / 128, BB * HH), 256, AT_SMEM>>>(
        qh, ql, kh, kl, vh, vl, ah, al);

    // Output projection -> d_out
    gemm_mma<0><<<dim3(EE / 128, MT / 128, 1), 256, GM_SMEM>>>(
        ah, al, wth, wtl, nullptr, nullptr, nullptr, bp,
        (float*)d_out, nullptr, nullptr);
}